// round 5
// baseline (speedup 1.0000x reference)
#include <cuda_runtime.h>
#include <cuda_bf16.h>
#include <cstdint>
#include <math.h>

#define N_NODES 100000
#define D 128
#define E_EDGES 1600000
#define EPS 1e-5f
#define NTILES ((N_NODES + 127) / 128)   // 782

// ---------------- scratch (device globals: no allocs allowed) ----------------
__device__ float  g_agg[(size_t)N_NODES * D];   // x + agg; then mid; then h2 (in-place)
__device__ double g_colsum[D];
__device__ double g_colsq [D];
__device__ float  g_scale[D];
__device__ float  g_shift[D];
__device__ int    g_idx_is64;

// ============================ helpers ========================================
__device__ __forceinline__ float to_tf32(float v) {
    float r;
    asm("cvt.rna.tf32.f32 %0, %1;" : "=f"(r) : "f"(v));
    return r;
}
// XOR-swizzled element index within a 128x128 tile (stride 128 floats).
__device__ __forceinline__ int idxA(int row, int col) {
    return row * 128 + (((col >> 2) ^ (row & 31)) << 2) + (col & 3);
}

__device__ __forceinline__ void mma_tf32(float c[4],
                                         uint32_t a0, uint32_t a1,
                                         uint32_t a2, uint32_t a3,
                                         uint32_t b0, uint32_t b1) {
    asm volatile(
        "mma.sync.aligned.m16n8k8.row.col.f32.tf32.tf32.f32 "
        "{%0,%1,%2,%3}, {%4,%5,%6,%7}, {%8,%9}, {%0,%1,%2,%3};"
        : "+f"(c[0]), "+f"(c[1]), "+f"(c[2]), "+f"(c[3])
        : "r"(a0), "r"(a1), "r"(a2), "r"(a3), "r"(b0), "r"(b1));
}

// ---------------- kernel 1: agg = x, zero BN accums, detect idx dtype -------
__global__ void init_kernel(const float* __restrict__ x,
                            const int* __restrict__ ei32) {
    size_t i = (size_t)blockIdx.x * blockDim.x + threadIdx.x;
    size_t n4 = (size_t)N_NODES * D / 4;
    if (i < n4)
        reinterpret_cast<float4*>(g_agg)[i] = reinterpret_cast<const float4*>(x)[i];
    if (blockIdx.x == 0 && threadIdx.x < D) {
        g_colsum[threadIdx.x] = 0.0;
        g_colsq [threadIdx.x] = 0.0;
    }
    if (blockIdx.x == 0 && threadIdx.x == 0) {
        int is64 = 1;
        #pragma unroll 1
        for (int k = 0; k < 128; k++)
            if (ei32[2 * k + 1] != 0) { is64 = 0; break; }
        g_idx_is64 = is64;
    }
}

// ---------------- kernel 2: scatter-add, one warp per edge ------------------
__device__ __forceinline__ void red_add_v4(float* addr, float4 v) {
    asm volatile("red.global.add.v4.f32 [%0], {%1,%2,%3,%4};"
                 :: "l"(addr), "f"(v.x), "f"(v.y), "f"(v.z), "f"(v.w) : "memory");
}
__global__ void scatter_kernel(const float* __restrict__ x,
                               const void* __restrict__ ei_raw) {
    int w    = (blockIdx.x * blockDim.x + threadIdx.x) >> 5;
    int lane = threadIdx.x & 31;
    if (w >= E_EDGES) return;
    int r, c;
    if (g_idx_is64) {
        const long long* ei = (const long long*)ei_raw;
        r = (int)__ldg(ei + w);
        c = (int)__ldg(ei + E_EDGES + w);
    } else {
        const int* ei = (const int*)ei_raw;
        r = __ldg(ei + w);
        c = __ldg(ei + E_EDGES + w);
    }
    float4 v = *reinterpret_cast<const float4*>(x + (size_t)c * D + lane * 4);
    red_add_v4(g_agg + (size_t)r * D + lane * 4, v);
}

// ---------------- stage kernel: in-place 128x128 GEMM via mma.sync tf32 -----
// io <- act(io @ W + b). 3-term tf32 split. 16 warps, each 32x32 output block.
#define STAGE_THREADS 512
#define SM_FLOATS (16384 + 16384 + (16384 + 16384) / 2 + 128 + 128 + 128)
#define SM_BYTES  (SM_FLOATS * 4)

__global__ __launch_bounds__(STAGE_THREADS, 1)
void stage_mma_kernel(const float* __restrict__ W, const float* __restrict__ bias,
                      int do_relu, int do_bn) {
    extern __shared__ float smf[];
    float* WHI = smf;                                   // [128][128] swizzled
    float* AHI = smf + 16384;                           // [128][128] swizzled (also out)
    __nv_bfloat16* WLO = (__nv_bfloat16*)(smf + 32768); // [128][128] swizzled
    __nv_bfloat16* ALO = WLO + 16384;
    float* BS = (float*)(ALO + 16384);                  // 128
    float* CS = BS + 128;                               // 128
    float* CQ = CS + 128;                               // 128

    const int tid    = threadIdx.x;
    const int lane   = tid & 31;
    const int warp   = tid >> 5;       // 0..15
    const int warp_m = warp & 3;       // 4 row-blocks of 32
    const int warp_n = warp >> 2;      // 4 col-blocks of 32
    const int gid    = lane >> 2;      // 0..7
    const int tig    = lane & 3;       // 0..3

    float* io = g_agg;

    // ---- load weights once: W[k][n] -> transposed swizzled hi(f32)/lo(bf16)
    for (int i4 = tid; i4 < 4096; i4 += STAGE_THREADS) {
        int k  = i4 >> 5;
        int c4 = i4 & 31;
        float4 v = ((const float4*)W)[i4];
        #pragma unroll
        for (int e = 0; e < 4; e++) {
            float val = (e == 0) ? v.x : (e == 1) ? v.y : (e == 2) ? v.z : v.w;
            int n = c4 * 4 + e;
            float hi = to_tf32(val);
            int o = idxA(n, k);
            WHI[o] = hi;
            WLO[o] = __float2bfloat16(val - hi);
        }
    }
    if (tid < 128) {
        BS[tid] = bias[tid];
        CS[tid] = 0.f;
        CQ[tid] = 0.f;
    }
    __syncthreads();

    for (int t = blockIdx.x; t < NTILES; t += gridDim.x) {
        const int base  = t << 7;
        const int valid = min(128, N_NODES - base);
        __syncthreads();   // protect AHI/ALO from previous tile's readers

        // ---- 1) load tile, split into Ahi (tf32) / Alo (bf16) --------------
        #pragma unroll
        for (int q = 0; q < 8; q++) {
            int f   = q * STAGE_THREADS + tid;
            int row = f >> 5, c4 = f & 31;
            float4 v = make_float4(0.f, 0.f, 0.f, 0.f);
            if (row < valid)
                v = ((const float4*)io)[(size_t)(base + row) * 32 + c4];
            float h0 = to_tf32(v.x), h1 = to_tf32(v.y);
            float h2 = to_tf32(v.z), h3 = to_tf32(v.w);
            int off = row * 128 + ((c4 ^ (row & 31)) << 2);
            *(float4*)(AHI + off) = make_float4(h0, h1, h2, h3);
            uint32_t p0 = ((uint32_t)__bfloat16_as_ushort(__float2bfloat16(v.y - h1)) << 16)
                        |  (uint32_t)__bfloat16_as_ushort(__float2bfloat16(v.x - h0));
            uint32_t p1 = ((uint32_t)__bfloat16_as_ushort(__float2bfloat16(v.w - h3)) << 16)
                        |  (uint32_t)__bfloat16_as_ushort(__float2bfloat16(v.z - h2));
            uint2 pk; pk.x = p0; pk.y = p1;
            *(uint2*)(ALO + off) = pk;
        }
        __syncthreads();

        // ---- 2) MMA mainloop: 32x32 block per warp ---------------------------
        float c[2][4][4];
        #pragma unroll
        for (int u = 0; u < 2; u++)
            #pragma unroll
            for (int j = 0; j < 4; j++)
                #pragma unroll
                for (int e = 0; e < 4; e++) c[u][j][e] = 0.f;

        const int mrow = warp_m * 32 + gid;
        const int nbas = warp_n * 32 + gid;

        #pragma unroll 1
        for (int s = 0; s < 16; s++) {
            const int kb = s << 3;
            uint32_t ah[2][4], al[2][4];
            #pragma unroll
            for (int u = 0; u < 2; u++) {
                int r0 = mrow + u * 16;
                ah[u][0] = __float_as_uint(AHI[idxA(r0,     kb + tig)]);
                ah[u][1] = __float_as_uint(AHI[idxA(r0 + 8, kb + tig)]);
                ah[u][2] = __float_as_uint(AHI[idxA(r0,     kb + 4 + tig)]);
                ah[u][3] = __float_as_uint(AHI[idxA(r0 + 8, kb + 4 + tig)]);
                al[u][0] = __float_as_uint(__bfloat162float(ALO[idxA(r0,     kb + tig)]));
                al[u][1] = __float_as_uint(__bfloat162float(ALO[idxA(r0 + 8, kb + tig)]));
                al[u][2] = __float_as_uint(__bfloat162float(ALO[idxA(r0,     kb + 4 + tig)]));
                al[u][3] = __float_as_uint(__bfloat162float(ALO[idxA(r0 + 8, kb + 4 + tig)]));
            }
            #pragma unroll
            for (int j = 0; j < 4; j++) {
                int n0 = nbas + j * 8;
                uint32_t bh0 = __float_as_uint(WHI[idxA(n0, kb + tig)]);
                uint32_t bh1 = __float_as_uint(WHI[idxA(n0, kb + 4 + tig)]);
                uint32_t bl0 = __float_as_uint(__bfloat162float(WLO[idxA(n0, kb + tig)]));
                uint32_t bl1 = __float_as_uint(__bfloat162float(WLO[idxA(n0, kb + 4 + tig)]));
                #pragma unroll
                for (int u = 0; u < 2; u++) {
                    mma_tf32(c[u][j], ah[u][0], ah[u][1], ah[u][2], ah[u][3], bh0, bh1);
                    mma_tf32(c[u][j], ah[u][0], ah[u][1], ah[u][2], ah[u][3], bl0, bl1);
                    mma_tf32(c[u][j], al[u][0], al[u][1], al[u][2], al[u][3], bh0, bh1);
                }
            }
        }
        __syncthreads();   // all warps done reading AHI/ALO

        // ---- 3) epilogue: bias (+relu) -> out tile (reuse AHI) --------------
        #pragma unroll
        for (int u = 0; u < 2; u++) {
            int r0 = mrow + u * 16;
            #pragma unroll
            for (int j = 0; j < 4; j++) {
                int cc = warp_n * 32 + j * 8 + 2 * tig;
                float v0 = c[u][j][0] + BS[cc];
                float v1 = c[u][j][1] + BS[cc + 1];
                float v2 = c[u][j][2] + BS[cc];
                float v3 = c[u][j][3] + BS[cc + 1];
                if (do_relu) {
                    v0 = fmaxf(v0, 0.f); v1 = fmaxf(v1, 0.f);
                    v2 = fmaxf(v2, 0.f); v3 = fmaxf(v3, 0.f);
                }
                *(float2*)&AHI[idxA(r0,     cc)] = make_float2(v0, v1);
                *(float2*)&AHI[idxA(r0 + 8, cc)] = make_float2(v2, v3);
            }
        }
        __syncthreads();

        // ---- 4) store tile (+ fused BN column sums in stage 2) --------------
        if (do_bn) {
            int col  = tid >> 2;           // 0..127
            int quar = tid & 3;
            int rbeg = quar * 32;
            int rend = min(rbeg + 32, valid);
            float s = 0.f, q = 0.f;
            for (int r = rbeg; r < rend; r++) {
                float v = AHI[idxA(r, col)];
                s += v; q += v * v;
            }
            atomicAdd(&CS[col], s);
            atomicAdd(&CQ[col], q);
        }
        #pragma unroll
        for (int q = 0; q < 8; q++) {
            int f   = q * STAGE_THREADS + tid;
            int row = f >> 5, c4 = f & 31;
            if (row < valid) {
                int off = row * 128 + ((c4 ^ (row & 31)) << 2);
                float4 v = *(const float4*)(AHI + off);
                ((float4*)io)[(size_t)(base + row) * 32 + c4] = v;
            }
        }
    }

    __syncthreads();
    if (do_bn && tid < 128) {
        atomicAdd(&g_colsum[tid], (double)CS[tid]);
        atomicAdd(&g_colsq [tid], (double)CQ[tid]);
    }
}

// ---------------- BN coefficients -------------------------------------------
__global__ void bn_prep_kernel(const float* __restrict__ gamma,
                               const float* __restrict__ beta) {
    int j = threadIdx.x;
    if (j < D) {
        double mean = g_colsum[j] / (double)N_NODES;
        double var  = g_colsq[j] / (double)N_NODES - mean * mean;
        float inv   = rsqrtf((float)var + EPS);
        float sc    = gamma[j] * inv;
        g_scale[j]  = sc;
        g_shift[j]  = beta[j] - (float)mean * sc;
    }
}

// ---------------- apply BN ----------------------------------------------------
__global__ void bn_apply_kernel(float* __restrict__ out) {
    __shared__ float sc[D], sh[D];
    if (threadIdx.x < D) {
        sc[threadIdx.x] = g_scale[threadIdx.x];
        sh[threadIdx.x] = g_shift[threadIdx.x];
    }
    __syncthreads();
    size_t i  = (size_t)blockIdx.x * blockDim.x + threadIdx.x;
    size_t n4 = (size_t)N_NODES * D / 4;
    if (i < n4) {
        int c = (int)((i & 31) << 2);
        float4 h = reinterpret_cast<const float4*>(g_agg)[i];
        float4 o;
        o.x = h.x * sc[c + 0] + sh[c + 0];
        o.y = h.y * sc[c + 1] + sh[c + 1];
        o.z = h.z * sc[c + 2] + sh[c + 2];
        o.w = h.w * sc[c + 3] + sh[c + 3];
        reinterpret_cast<float4*>(out)[i] = o;
    }
}

// ---------------- launcher ----------------------------------------------------
extern "C" void kernel_launch(void* const* d_in, const int* in_sizes, int n_in,
                              void* d_out, int out_size) {
    const float* x     = (const float*)d_in[0];
    const void*  ei    = d_in[1];
    const float* W1    = (const float*)d_in[2];
    const float* b1    = (const float*)d_in[3];
    const float* W2    = (const float*)d_in[4];
    const float* b2    = (const float*)d_in[5];
    const float* gamma = (const float*)d_in[6];
    const float* beta  = (const float*)d_in[7];
    float* out = (float*)d_out;

    cudaFuncSetAttribute(stage_mma_kernel,
                         cudaFuncAttributeMaxDynamicSharedMemorySize, SM_BYTES);

    {
        int n4 = N_NODES * D / 4;
        init_kernel<<<(n4 + 255) / 256, 256>>>(x, (const int*)ei);
    }
    {
        int blocks = (E_EDGES + 7) / 8;   // 8 warps (256 threads) per block
        scatter_kernel<<<blocks, 256>>>(x, ei);
    }
    stage_mma_kernel<<<152, STAGE_THREADS, SM_BYTES>>>(W1, b1, 1, 0);
    stage_mma_kernel<<<152, STAGE_THREADS, SM_BYTES>>>(W2, b2, 0, 1);
    bn_prep_kernel<<<1, 128>>>(gamma, beta);
    {
        int n4 = N_NODES * D / 4;
        bn_apply_kernel<<<(n4 + 255) / 256, 256>>>(out);
    }
}

// round 6
// speedup vs baseline: 1.1670x; 1.1670x over previous
#include <cuda_runtime.h>
#include <cuda_bf16.h>
#include <cstdint>
#include <math.h>

#define N_NODES 100000
#define D 128
#define E_EDGES 1600000
#define EPS 1e-5f
#define NTILES ((N_NODES + 127) / 128)   // 782

// ---------------- scratch (device globals: no allocs allowed) ----------------
__device__ float  g_agg[(size_t)N_NODES * D];   // x + agg; then mid; then h2 (in-place)
__device__ double g_colsum[D];
__device__ double g_colsq [D];
__device__ float  g_scale[D];
__device__ float  g_shift[D];
__device__ int    g_idx_is64;

// ============================ helpers ========================================
__device__ __forceinline__ uint32_t smem_u32(const void* p) {
    uint32_t a;
    asm("{ .reg .u64 t; cvta.to.shared.u64 t, %1; cvt.u32.u64 %0, t; }"
        : "=r"(a) : "l"(p));
    return a;
}
// bf16 tile (128 rows x 128 cols, 256B/row) swizzled byte offset.
// j = 16B chunk index (0..15). XOR low 3 bits of j with row&7 -> ldmatrix
// phases (8 rows x 16B) hit 8 distinct 16B banks.
__device__ __forceinline__ int bswz(int r, int j) {
    return r * 256 + ((((j ^ r) & 7) | (j & 8)) << 4);
}
// f32 out tile swizzle (float index), as in prior rounds
__device__ __forceinline__ int idxA(int row, int col) {
    return row * 128 + (((col >> 2) ^ (row & 31)) << 2) + (col & 3);
}

__device__ __forceinline__ void ldmx4(uint32_t r[4], uint32_t addr) {
    asm volatile("ldmatrix.sync.aligned.m8n8.x4.shared.b16 {%0,%1,%2,%3}, [%4];"
                 : "=r"(r[0]), "=r"(r[1]), "=r"(r[2]), "=r"(r[3]) : "r"(addr));
}
__device__ __forceinline__ void mma_bf16(float c[4], const uint32_t a[4],
                                         uint32_t b0, uint32_t b1) {
    asm volatile(
        "mma.sync.aligned.m16n8k16.row.col.f32.bf16.bf16.f32 "
        "{%0,%1,%2,%3}, {%4,%5,%6,%7}, {%8,%9}, {%0,%1,%2,%3};"
        : "+f"(c[0]), "+f"(c[1]), "+f"(c[2]), "+f"(c[3])
        : "r"(a[0]), "r"(a[1]), "r"(a[2]), "r"(a[3]), "r"(b0), "r"(b1));
}

// ---------------- kernel 1: agg = x, zero BN accums, detect idx dtype -------
__global__ void init_kernel(const float* __restrict__ x,
                            const int* __restrict__ ei32) {
    size_t i = (size_t)blockIdx.x * blockDim.x + threadIdx.x;
    size_t n4 = (size_t)N_NODES * D / 4;
    if (i < n4)
        reinterpret_cast<float4*>(g_agg)[i] = reinterpret_cast<const float4*>(x)[i];
    if (blockIdx.x == 0 && threadIdx.x < D) {
        g_colsum[threadIdx.x] = 0.0;
        g_colsq [threadIdx.x] = 0.0;
    }
    if (blockIdx.x == 0 && threadIdx.x == 0) {
        int is64 = 1;
        #pragma unroll 1
        for (int k = 0; k < 128; k++)
            if (ei32[2 * k + 1] != 0) { is64 = 0; break; }
        g_idx_is64 = is64;
    }
}

// ---------------- kernel 2: scatter-add, one warp per edge ------------------
__device__ __forceinline__ void red_add_v4(float* addr, float4 v) {
    asm volatile("red.global.add.v4.f32 [%0], {%1,%2,%3,%4};"
                 :: "l"(addr), "f"(v.x), "f"(v.y), "f"(v.z), "f"(v.w) : "memory");
}
__global__ void scatter_kernel(const float* __restrict__ x,
                               const void* __restrict__ ei_raw) {
    int w    = (blockIdx.x * blockDim.x + threadIdx.x) >> 5;
    int lane = threadIdx.x & 31;
    if (w >= E_EDGES) return;
    int r, c;
    if (g_idx_is64) {
        const long long* ei = (const long long*)ei_raw;
        r = (int)__ldg(ei + w);
        c = (int)__ldg(ei + E_EDGES + w);
    } else {
        const int* ei = (const int*)ei_raw;
        r = __ldg(ei + w);
        c = __ldg(ei + E_EDGES + w);
    }
    float4 v = *reinterpret_cast<const float4*>(x + (size_t)c * D + lane * 4);
    red_add_v4(g_agg + (size_t)r * D + lane * 4, v);
}

// ---------------- stage kernel: in-place 128x128 GEMM, bf16 hi/lo + ldmatrix
// io <- act(io @ W + b). 3-term split: AhiWhi + AhiWlo + AloWhi (f32 accum).
#define STAGE_THREADS 512
// byte offsets in dynamic smem
#define SO_AHI  0          // bf16 [128][128] 32768B
#define SO_ALO  32768
#define SO_WHI  65536
#define SO_WLO  98304
#define SO_OUT  131072     // f32 [128][128] 65536B
#define SO_BS   196608
#define SO_CS   197120
#define SO_CQ   197632
#define SM_BYTES 198144

__global__ __launch_bounds__(STAGE_THREADS, 1)
void stage_mma_kernel(const float* __restrict__ W, const float* __restrict__ bias,
                      int do_relu, int do_bn) {
    extern __shared__ char smc[];
    float* OUT = (float*)(smc + SO_OUT);
    float* BS  = (float*)(smc + SO_BS);
    float* CS  = (float*)(smc + SO_CS);
    float* CQ  = (float*)(smc + SO_CQ);
    const uint32_t sb = smem_u32(smc);

    const int tid    = threadIdx.x;
    const int lane   = tid & 31;
    const int warp   = tid >> 5;       // 0..15
    const int warp_m = warp & 3;       // 4 row-blocks of 32
    const int warp_n = warp >> 2;      // 4 col-blocks of 32
    const int gid    = lane >> 2;
    const int tig    = lane & 3;

    float* io = g_agg;

    // ---- load weights once: W[k][n] -> WHI/WLO[n][k] (bf16, swizzled) ------
    for (int i4 = tid; i4 < 4096; i4 += STAGE_THREADS) {
        int k  = i4 >> 5;
        int c4 = i4 & 31;
        float4 v = ((const float4*)W)[i4];
        #pragma unroll
        for (int e = 0; e < 4; e++) {
            float val = (e == 0) ? v.x : (e == 1) ? v.y : (e == 2) ? v.z : v.w;
            int n = c4 * 4 + e;
            __nv_bfloat16 hi = __float2bfloat16(val);
            __nv_bfloat16 lo = __float2bfloat16(val - __bfloat162float(hi));
            int off = bswz(n, k >> 3) + (k & 7) * 2;
            *(__nv_bfloat16*)(smc + SO_WHI + off) = hi;
            *(__nv_bfloat16*)(smc + SO_WLO + off) = lo;
        }
    }
    if (tid < 128) {
        BS[tid] = bias[tid];
        CS[tid] = 0.f;
        CQ[tid] = 0.f;
    }
    __syncthreads();

    // per-lane fragment row constants
    const int rA0 = warp_m * 32 + (lane & 15);
    const int jAh = lane >> 4;                       // A k-chunk half
    const int rB0 = warp_n * 32 + (lane & 7) + ((lane >> 4) << 3);
    const int jBh = (lane >> 3) & 1;                 // B k-chunk half

    for (int t = blockIdx.x; t < NTILES; t += gridDim.x) {
        const int base  = t << 7;
        const int valid = min(128, N_NODES - base);

        // ---- 1) load tile, split to AHI/ALO bf16 (swizzled) -----------------
        #pragma unroll
        for (int q = 0; q < 4; q++) {
            int f   = q * STAGE_THREADS + tid;       // 2048 chunks of 8 floats
            int row = f >> 4, j = f & 15;
            float4 v0 = make_float4(0.f, 0.f, 0.f, 0.f), v1 = v0;
            if (row < valid) {
                const float4* src = (const float4*)io + (size_t)(base + row) * 32 + j * 2;
                v0 = src[0]; v1 = src[1];
            }
            float vv[8] = {v0.x, v0.y, v0.z, v0.w, v1.x, v1.y, v1.z, v1.w};
            uint32_t ph[4], pl[4];
            #pragma unroll
            for (int e = 0; e < 4; e++) {
                __nv_bfloat16 h0 = __float2bfloat16(vv[2 * e]);
                __nv_bfloat16 h1 = __float2bfloat16(vv[2 * e + 1]);
                __nv_bfloat16 l0 = __float2bfloat16(vv[2 * e]     - __bfloat162float(h0));
                __nv_bfloat16 l1 = __float2bfloat16(vv[2 * e + 1] - __bfloat162float(h1));
                ph[e] = (uint32_t)__bfloat16_as_ushort(h0)
                      | ((uint32_t)__bfloat16_as_ushort(h1) << 16);
                pl[e] = (uint32_t)__bfloat16_as_ushort(l0)
                      | ((uint32_t)__bfloat16_as_ushort(l1) << 16);
            }
            int off = bswz(row, j);
            *(uint4*)(smc + SO_AHI + off) = make_uint4(ph[0], ph[1], ph[2], ph[3]);
            *(uint4*)(smc + SO_ALO + off) = make_uint4(pl[0], pl[1], pl[2], pl[3]);
        }
        __syncthreads();

        // ---- 2) MMA mainloop: 32x32 per warp, ldmatrix fragments ------------
        float c[2][4][4];
        #pragma unroll
        for (int u = 0; u < 2; u++)
            #pragma unroll
            for (int j = 0; j < 4; j++)
                #pragma unroll
                for (int e = 0; e < 4; e++) c[u][j][e] = 0.f;

        #pragma unroll 1
        for (int s = 0; s < 8; s++) {                 // k16 steps
            int jA = (s << 1) | jAh;
            uint32_t offA = (uint32_t)(rA0 * 256 + ((((jA ^ rA0) & 7) | (jA & 8)) << 4));
            int jB = (s << 1) | jBh;
            uint32_t offB = (uint32_t)(rB0 * 256 + ((((jB ^ rB0) & 7) | (jB & 8)) << 4));

            uint32_t ah[2][4], al[2][4], bh[2][4], bl[2][4];
            ldmx4(ah[0], sb + SO_AHI + offA);
            ldmx4(ah[1], sb + SO_AHI + offA + 4096);   // rows +16, same swizzle bits
            ldmx4(al[0], sb + SO_ALO + offA);
            ldmx4(al[1], sb + SO_ALO + offA + 4096);
            ldmx4(bh[0], sb + SO_WHI + offB);
            ldmx4(bh[1], sb + SO_WHI + offB + 4096);
            ldmx4(bl[0], sb + SO_WLO + offB);
            ldmx4(bl[1], sb + SO_WLO + offB + 4096);

            #pragma unroll
            for (int j = 0; j < 4; j++) {
                int p = j >> 1, q2 = (j & 1) << 1;
                uint32_t b0h = bh[p][q2], b1h = bh[p][q2 + 1];
                uint32_t b0l = bl[p][q2], b1l = bl[p][q2 + 1];
                #pragma unroll
                for (int u = 0; u < 2; u++) {
                    mma_bf16(c[u][j], ah[u], b0h, b1h);
                    mma_bf16(c[u][j], ah[u], b0l, b1l);
                    mma_bf16(c[u][j], al[u], b0h, b1h);
                }
            }
        }
        __syncthreads();   // all warps done reading AHI/ALO before OUT reuse cycle

        // ---- 3) epilogue: bias (+relu) -> OUT (f32 swizzled) ----------------
        #pragma unroll
        for (int u = 0; u < 2; u++) {
            int r0 = warp_m * 32 + u * 16 + gid;
            #pragma unroll
            for (int j = 0; j < 4; j++) {
                int cc = warp_n * 32 + j * 8 + tig * 2;
                float v0 = c[u][j][0] + BS[cc];
                float v1 = c[u][j][1] + BS[cc + 1];
                float v2 = c[u][j][2] + BS[cc];
                float v3 = c[u][j][3] + BS[cc + 1];
                if (do_relu) {
                    v0 = fmaxf(v0, 0.f); v1 = fmaxf(v1, 0.f);
                    v2 = fmaxf(v2, 0.f); v3 = fmaxf(v3, 0.f);
                }
                *(float2*)&OUT[idxA(r0,     cc)] = make_float2(v0, v1);
                *(float2*)&OUT[idxA(r0 + 8, cc)] = make_float2(v2, v3);
            }
        }
        __syncthreads();

        // ---- 4) store tile (+ fused BN column sums) -------------------------
        if (do_bn) {
            int col  = tid >> 2;
            int quar = tid & 3;
            int rbeg = quar * 32;
            int rend = min(rbeg + 32, valid);
            float s = 0.f, q = 0.f;
            for (int r = rbeg; r < rend; r++) {
                float v = OUT[idxA(r, col)];
                s += v; q += v * v;
            }
            atomicAdd(&CS[col], s);
            atomicAdd(&CQ[col], q);
        }
        #pragma unroll
        for (int q = 0; q < 8; q++) {
            int f   = q * STAGE_THREADS + tid;
            int row = f >> 5, c4 = f & 31;
            if (row < valid) {
                int off = row * 128 + ((c4 ^ (row & 31)) << 2);
                float4 v = *(const float4*)(OUT + off);
                ((float4*)io)[(size_t)(base + row) * 32 + c4] = v;
            }
        }
        __syncthreads();   // OUT fully consumed before next tile's epilogue
    }

    if (do_bn && tid < 128) {
        atomicAdd(&g_colsum[tid], (double)CS[tid]);
        atomicAdd(&g_colsq [tid], (double)CQ[tid]);
    }
}

// ---------------- BN coefficients -------------------------------------------
__global__ void bn_prep_kernel(const float* __restrict__ gamma,
                               const float* __restrict__ beta) {
    int j = threadIdx.x;
    if (j < D) {
        double mean = g_colsum[j] / (double)N_NODES;
        double var  = g_colsq[j] / (double)N_NODES - mean * mean;
        float inv   = rsqrtf((float)var + EPS);
        float sc    = gamma[j] * inv;
        g_scale[j]  = sc;
        g_shift[j]  = beta[j] - (float)mean * sc;
    }
}

// ---------------- apply BN ----------------------------------------------------
__global__ void bn_apply_kernel(float* __restrict__ out) {
    __shared__ float sc[D], sh[D];
    if (threadIdx.x < D) {
        sc[threadIdx.x] = g_scale[threadIdx.x];
        sh[threadIdx.x] = g_shift[threadIdx.x];
    }
    __syncthreads();
    size_t i  = (size_t)blockIdx.x * blockDim.x + threadIdx.x;
    size_t n4 = (size_t)N_NODES * D / 4;
    if (i < n4) {
        int c = (int)((i & 31) << 2);
        float4 h = reinterpret_cast<const float4*>(g_agg)[i];
        float4 o;
        o.x = h.x * sc[c + 0] + sh[c + 0];
        o.y = h.y * sc[c + 1] + sh[c + 1];
        o.z = h.z * sc[c + 2] + sh[c + 2];
        o.w = h.w * sc[c + 3] + sh[c + 3];
        reinterpret_cast<float4*>(out)[i] = o;
    }
}

// ---------------- launcher ----------------------------------------------------
extern "C" void kernel_launch(void* const* d_in, const int* in_sizes, int n_in,
                              void* d_out, int out_size) {
    const float* x     = (const float*)d_in[0];
    const void*  ei    = d_in[1];
    const float* W1    = (const float*)d_in[2];
    const float* b1    = (const float*)d_in[3];
    const float* W2    = (const float*)d_in[4];
    const float* b2    = (const float*)d_in[5];
    const float* gamma = (const float*)d_in[6];
    const float* beta  = (const float*)d_in[7];
    float* out = (float*)d_out;

    cudaFuncSetAttribute(stage_mma_kernel,
                         cudaFuncAttributeMaxDynamicSharedMemorySize, SM_BYTES);

    {
        int n4 = N_NODES * D / 4;
        init_kernel<<<(n4 + 255) / 256, 256>>>(x, (const int*)ei);
    }
    {
        int blocks = (E_EDGES + 7) / 8;   // 8 warps (256 threads) per block
        scatter_kernel<<<blocks, 256>>>(x, ei);
    }
    stage_mma_kernel<<<152, STAGE_THREADS, SM_BYTES>>>(W1, b1, 1, 0);
    stage_mma_kernel<<<152, STAGE_THREADS, SM_BYTES>>>(W2, b2, 0, 1);
    bn_prep_kernel<<<1, 128>>>(gamma, beta);
    {
        int n4 = N_NODES * D / 4;
        bn_apply_kernel<<<(n4 + 255) / 256, 256>>>(out);
    }
}

// round 7
// speedup vs baseline: 1.2079x; 1.0350x over previous
#include <cuda_runtime.h>
#include <cuda_bf16.h>
#include <cstdint>
#include <math.h>

#define N_NODES 100000
#define D 128
#define E_EDGES 1600000
#define EPS 1e-5f
#define NTILES ((N_NODES + 127) / 128)   // 782

// ---------------- scratch (device globals: no allocs allowed) ----------------
__device__ float  g_agg[(size_t)N_NODES * D];   // x + agg; then mid; then h2 (in-place)
__device__ double g_colsum[D];
__device__ double g_colsq [D];
__device__ float  g_scale[D];
__device__ float  g_shift[D];
__device__ int    g_idx_is64;

// ============================ helpers ========================================
__device__ __forceinline__ uint32_t smem_u32(const void* p) {
    uint32_t a;
    asm("{ .reg .u64 t; cvta.to.shared.u64 t, %1; cvt.u32.u64 %0, t; }"
        : "=r"(a) : "l"(p));
    return a;
}
// bf16 tile (128 rows x 128 cols, 256B/row) swizzled byte offset, j = 16B chunk
__device__ __forceinline__ int bswz(int r, int j) {
    return r * 256 + ((((j ^ r) & 7) | (j & 8)) << 4);
}
// f32 out tile swizzle (float index)
__device__ __forceinline__ int idxA(int row, int col) {
    return row * 128 + (((col >> 2) ^ (row & 31)) << 2) + (col & 3);
}

__device__ __forceinline__ void ldmx4(uint32_t r[4], uint32_t addr) {
    asm volatile("ldmatrix.sync.aligned.m8n8.x4.shared.b16 {%0,%1,%2,%3}, [%4];"
                 : "=r"(r[0]), "=r"(r[1]), "=r"(r[2]), "=r"(r[3]) : "r"(addr));
}
__device__ __forceinline__ void mma_bf16(float c[4], const uint32_t a[4],
                                         uint32_t b0, uint32_t b1) {
    asm volatile(
        "mma.sync.aligned.m16n8k16.row.col.f32.bf16.bf16.f32 "
        "{%0,%1,%2,%3}, {%4,%5,%6,%7}, {%8,%9}, {%0,%1,%2,%3};"
        : "+f"(c[0]), "+f"(c[1]), "+f"(c[2]), "+f"(c[3])
        : "r"(a[0]), "r"(a[1]), "r"(a[2]), "r"(a[3]), "r"(b0), "r"(b1));
}
__device__ __forceinline__ void cp_async16(uint32_t s, const void* g, int src_sz) {
    asm volatile("cp.async.cg.shared.global [%0], [%1], 16, %2;"
                 :: "r"(s), "l"(g), "r"(src_sz) : "memory");
}
__device__ __forceinline__ void cp_commit() {
    asm volatile("cp.async.commit_group;" ::: "memory");
}
__device__ __forceinline__ void cp_wait0() {
    asm volatile("cp.async.wait_group 0;" ::: "memory");
}

// ---------------- kernel 1: agg = x, zero BN accums, detect idx dtype -------
__global__ void init_kernel(const float* __restrict__ x,
                            const int* __restrict__ ei32) {
    size_t i = (size_t)blockIdx.x * blockDim.x + threadIdx.x;
    size_t n4 = (size_t)N_NODES * D / 4;
    if (i < n4)
        reinterpret_cast<float4*>(g_agg)[i] = reinterpret_cast<const float4*>(x)[i];
    if (blockIdx.x == 0 && threadIdx.x < D) {
        g_colsum[threadIdx.x] = 0.0;
        g_colsq [threadIdx.x] = 0.0;
    }
    if (blockIdx.x == 0 && threadIdx.x == 0) {
        int is64 = 1;
        #pragma unroll 1
        for (int k = 0; k < 128; k++)
            if (ei32[2 * k + 1] != 0) { is64 = 0; break; }
        g_idx_is64 = is64;
    }
}

// ---------------- kernel 2: scatter-add, one warp per edge ------------------
__device__ __forceinline__ void red_add_v4(float* addr, float4 v) {
    asm volatile("red.global.add.v4.f32 [%0], {%1,%2,%3,%4};"
                 :: "l"(addr), "f"(v.x), "f"(v.y), "f"(v.z), "f"(v.w) : "memory");
}
__global__ void scatter_kernel(const float* __restrict__ x,
                               const void* __restrict__ ei_raw) {
    int w    = (blockIdx.x * blockDim.x + threadIdx.x) >> 5;
    int lane = threadIdx.x & 31;
    if (w >= E_EDGES) return;
    int r, c;
    if (g_idx_is64) {
        const long long* ei = (const long long*)ei_raw;
        r = (int)__ldg(ei + w);
        c = (int)__ldg(ei + E_EDGES + w);
    } else {
        const int* ei = (const int*)ei_raw;
        r = __ldg(ei + w);
        c = __ldg(ei + E_EDGES + w);
    }
    float4 v = *reinterpret_cast<const float4*>(x + (size_t)c * D + lane * 4);
    red_add_v4(g_agg + (size_t)r * D + lane * 4, v);
}

// ---------------- stage kernel: pipelined in-place 128x128 GEMM -------------
// io <- act(io @ W + b). bf16 hi/lo 3-term split, ldmatrix fragments,
// cp.async one-tile-ahead prefetch. OUT aliases AHI/ALO.
#define STAGE_THREADS 512
#define SO_A    0          // AHI 0..32767 | ALO 32768..65535 ; OUT f32 aliases 0..65535
#define SO_WHI  65536
#define SO_WLO  98304
#define SO_STG  131072     // raw f32 tile staging, 65536B
#define SO_BS   196608
#define SO_CS   197120
#define SO_CQ   197632
#define SM_BYTES 198144

__global__ __launch_bounds__(STAGE_THREADS, 1)
void stage_mma_kernel(const float* __restrict__ W, const float* __restrict__ bias,
                      int do_relu, int do_bn) {
    extern __shared__ char smc[];
    float* OUT = (float*)(smc + SO_A);
    float* STG = (float*)(smc + SO_STG);
    float* BS  = (float*)(smc + SO_BS);
    float* CS  = (float*)(smc + SO_CS);
    float* CQ  = (float*)(smc + SO_CQ);
    const uint32_t sb = smem_u32(smc);

    const int tid    = threadIdx.x;
    const int lane   = tid & 31;
    const int warp   = tid >> 5;       // 0..15
    const int warp_m = warp & 3;
    const int warp_n = warp >> 2;
    const int gid    = lane >> 2;
    const int tig    = lane & 3;

    float* io = g_agg;

    // ---- load weights once: W[k][n] -> WHI/WLO[n][k] (bf16, swizzled) ------
    for (int i4 = tid; i4 < 4096; i4 += STAGE_THREADS) {
        int k  = i4 >> 5;
        int c4 = i4 & 31;
        float4 v = ((const float4*)W)[i4];
        #pragma unroll
        for (int e = 0; e < 4; e++) {
            float val = (e == 0) ? v.x : (e == 1) ? v.y : (e == 2) ? v.z : v.w;
            int n = c4 * 4 + e;
            __nv_bfloat16 hi = __float2bfloat16(val);
            __nv_bfloat16 lo = __float2bfloat16(val - __bfloat162float(hi));
            int off = bswz(n, k >> 3) + (k & 7) * 2;
            *(__nv_bfloat16*)(smc + SO_WHI + off) = hi;
            *(__nv_bfloat16*)(smc + SO_WLO + off) = lo;
        }
    }
    if (tid < 128) {
        BS[tid] = bias[tid];
        CS[tid] = 0.f;
        CQ[tid] = 0.f;
    }

    // ---- prologue: prefetch first tile into STG -----------------------------
    {
        int t0 = blockIdx.x;
        if (t0 < NTILES) {
            int base = t0 << 7;
            #pragma unroll
            for (int q = 0; q < 8; q++) {
                int ch  = q * STAGE_THREADS + tid;      // 16B chunk id (0..4095)
                int row = ch >> 5, c4 = ch & 31;
                int sz  = (base + row < N_NODES) ? 16 : 0;
                cp_async16(sb + SO_STG + ch * 16,
                           (const float4*)io + (size_t)(base + row) * 32 + c4, sz);
            }
        }
        cp_commit();
    }

    const int rA0 = warp_m * 32 + (lane & 15);
    const int jAh = lane >> 4;
    const int rB0 = warp_n * 32 + (lane & 7) + ((lane >> 4) << 3);
    const int jBh = (lane >> 3) & 1;

    for (int t = blockIdx.x; t < NTILES; t += gridDim.x) {
        const int base  = t << 7;
        const int valid = min(128, N_NODES - base);

        cp_wait0();
        __syncthreads();   // STG ready; OUT fully stored (prev iter)

        // ---- 1) split STG -> AHI/ALO bf16 (swizzled) ------------------------
        #pragma unroll
        for (int q = 0; q < 4; q++) {
            int f   = q * STAGE_THREADS + tid;        // 2048 chunks of 8 floats
            int row = f >> 4, j = f & 15;
            const float4* src = (const float4*)(STG + row * 128 + j * 8);
            float4 v0 = src[0], v1 = src[1];
            float vv[8] = {v0.x, v0.y, v0.z, v0.w, v1.x, v1.y, v1.z, v1.w};
            uint32_t ph[4], pl[4];
            #pragma unroll
            for (int e = 0; e < 4; e++) {
                __nv_bfloat16 h0 = __float2bfloat16(vv[2 * e]);
                __nv_bfloat16 h1 = __float2bfloat16(vv[2 * e + 1]);
                __nv_bfloat16 l0 = __float2bfloat16(vv[2 * e]     - __bfloat162float(h0));
                __nv_bfloat16 l1 = __float2bfloat16(vv[2 * e + 1] - __bfloat162float(h1));
                ph[e] = (uint32_t)__bfloat16_as_ushort(h0)
                      | ((uint32_t)__bfloat16_as_ushort(h1) << 16);
                pl[e] = (uint32_t)__bfloat16_as_ushort(l0)
                      | ((uint32_t)__bfloat16_as_ushort(l1) << 16);
            }
            int off = bswz(row, j);
            *(uint4*)(smc + SO_A + off)         = make_uint4(ph[0], ph[1], ph[2], ph[3]);
            *(uint4*)(smc + SO_A + 32768 + off) = make_uint4(pl[0], pl[1], pl[2], pl[3]);
        }
        __syncthreads();   // split done; STG free

        // ---- 1b) prefetch NEXT tile into STG (overlaps MMA/epilogue/store) --
        {
            int tn = t + gridDim.x;
            if (tn < NTILES) {
                int nb = tn << 7;
                #pragma unroll
                for (int q = 0; q < 8; q++) {
                    int ch  = q * STAGE_THREADS + tid;
                    int row = ch >> 5, c4 = ch & 31;
                    int sz  = (nb + row < N_NODES) ? 16 : 0;
                    cp_async16(sb + SO_STG + ch * 16,
                               (const float4*)io + (size_t)(nb + row) * 32 + c4, sz);
                }
            }
            cp_commit();
        }

        // ---- 2) MMA mainloop: 32x32 per warp --------------------------------
        float c[2][4][4];
        #pragma unroll
        for (int u = 0; u < 2; u++)
            #pragma unroll
            for (int j = 0; j < 4; j++)
                #pragma unroll
                for (int e = 0; e < 4; e++) c[u][j][e] = 0.f;

        #pragma unroll 2
        for (int s = 0; s < 8; s++) {
            int jA = (s << 1) | jAh;
            uint32_t offA = (uint32_t)(rA0 * 256 + ((((jA ^ rA0) & 7) | (jA & 8)) << 4));
            int jB = (s << 1) | jBh;
            uint32_t offB = (uint32_t)(rB0 * 256 + ((((jB ^ rB0) & 7) | (jB & 8)) << 4));

            uint32_t ah[2][4], al[2][4], bh[2][4], bl[2][4];
            ldmx4(ah[0], sb + SO_A + offA);
            ldmx4(ah[1], sb + SO_A + offA + 4096);
            ldmx4(al[0], sb + SO_A + 32768 + offA);
            ldmx4(al[1], sb + SO_A + 32768 + offA + 4096);
            ldmx4(bh[0], sb + SO_WHI + offB);
            ldmx4(bh[1], sb + SO_WHI + offB + 4096);
            ldmx4(bl[0], sb + SO_WLO + offB);
            ldmx4(bl[1], sb + SO_WLO + offB + 4096);

            #pragma unroll
            for (int j = 0; j < 4; j++) {
                int p = j >> 1, q2 = (j & 1) << 1;
                uint32_t b0h = bh[p][q2], b1h = bh[p][q2 + 1];
                uint32_t b0l = bl[p][q2], b1l = bl[p][q2 + 1];
                #pragma unroll
                for (int u = 0; u < 2; u++) {
                    mma_bf16(c[u][j], ah[u], b0h, b1h);
                    mma_bf16(c[u][j], ah[u], b0l, b1l);
                    mma_bf16(c[u][j], al[u], b0h, b1h);
                }
            }
        }
        __syncthreads();   // all warps done reading AHI/ALO -> OUT may overwrite

        // ---- 3) epilogue: bias (+relu) -> OUT (aliases AHI/ALO) -------------
        #pragma unroll
        for (int u = 0; u < 2; u++) {
            int r0 = warp_m * 32 + u * 16 + gid;
            #pragma unroll
            for (int j = 0; j < 4; j++) {
                int cc = warp_n * 32 + j * 8 + tig * 2;
                float v0 = c[u][j][0] + BS[cc];
                float v1 = c[u][j][1] + BS[cc + 1];
                float v2 = c[u][j][2] + BS[cc];
                float v3 = c[u][j][3] + BS[cc + 1];
                if (do_relu) {
                    v0 = fmaxf(v0, 0.f); v1 = fmaxf(v1, 0.f);
                    v2 = fmaxf(v2, 0.f); v3 = fmaxf(v3, 0.f);
                }
                *(float2*)&OUT[idxA(r0,     cc)] = make_float2(v0, v1);
                *(float2*)&OUT[idxA(r0 + 8, cc)] = make_float2(v2, v3);
            }
        }
        __syncthreads();

        // ---- 4) store tile (+ fused BN column sums) -------------------------
        if (do_bn) {
            int col  = tid >> 2;
            int quar = tid & 3;
            int rbeg = quar * 32;
            int rend = min(rbeg + 32, valid);
            float s = 0.f, q = 0.f;
            for (int r = rbeg; r < rend; r++) {
                float v = OUT[idxA(r, col)];
                s += v; q += v * v;
            }
            atomicAdd(&CS[col], s);
            atomicAdd(&CQ[col], q);
        }
        #pragma unroll
        for (int q = 0; q < 8; q++) {
            int f   = q * STAGE_THREADS + tid;
            int row = f >> 5, c4 = f & 31;
            if (row < valid) {
                int off = row * 128 + ((c4 ^ (row & 31)) << 2);
                float4 v = *(const float4*)(OUT + off);
                ((float4*)io)[(size_t)(base + row) * 32 + c4] = v;
            }
        }
        // next iteration's top sync orders OUT reuse vs. split writes
    }

    __syncthreads();
    if (do_bn && tid < 128) {
        atomicAdd(&g_colsum[tid], (double)CS[tid]);
        atomicAdd(&g_colsq [tid], (double)CQ[tid]);
    }
}

// ---------------- BN coefficients -------------------------------------------
__global__ void bn_prep_kernel(const float* __restrict__ gamma,
                               const float* __restrict__ beta) {
    int j = threadIdx.x;
    if (j < D) {
        double mean = g_colsum[j] / (double)N_NODES;
        double var  = g_colsq[j] / (double)N_NODES - mean * mean;
        float inv   = rsqrtf((float)var + EPS);
        float sc    = gamma[j] * inv;
        g_scale[j]  = sc;
        g_shift[j]  = beta[j] - (float)mean * sc;
    }
}

// ---------------- apply BN ----------------------------------------------------
__global__ void bn_apply_kernel(float* __restrict__ out) {
    __shared__ float sc[D], sh[D];
    if (threadIdx.x < D) {
        sc[threadIdx.x] = g_scale[threadIdx.x];
        sh[threadIdx.x] = g_shift[threadIdx.x];
    }
    __syncthreads();
    size_t i  = (size_t)blockIdx.x * blockDim.x + threadIdx.x;
    size_t n4 = (size_t)N_NODES * D / 4;
    if (i < n4) {
        int c = (int)((i & 31) << 2);
        float4 h = reinterpret_cast<const float4*>(g_agg)[i];
        float4 o;
        o.x = h.x * sc[c + 0] + sh[c + 0];
        o.y = h.y * sc[c + 1] + sh[c + 1];
        o.z = h.z * sc[c + 2] + sh[c + 2];
        o.w = h.w * sc[c + 3] + sh[c + 3];
        reinterpret_cast<float4*>(out)[i] = o;
    }
}

// ---------------- launcher ----------------------------------------------------
extern "C" void kernel_launch(void* const* d_in, const int* in_sizes, int n_in,
                              void* d_out, int out_size) {
    const float* x     = (const float*)d_in[0];
    const void*  ei    = d_in[1];
    const float* W1    = (const float*)d_in[2];
    const float* b1    = (const float*)d_in[3];
    const float* W2    = (const float*)d_in[4];
    const float* b2    = (const float*)d_in[5];
    const float* gamma = (const float*)d_in[6];
    const float* beta  = (const float*)d_in[7];
    float* out = (float*)d_out;

    cudaFuncSetAttribute(stage_mma_kernel,
                         cudaFuncAttributeMaxDynamicSharedMemorySize, SM_BYTES);

    {
        int n4 = N_NODES * D / 4;
        init_kernel<<<(n4 + 255) / 256, 256>>>(x, (const int*)ei);
    }
    {
        int blocks = (E_EDGES + 7) / 8;   // 8 warps (256 threads) per block
        scatter_kernel<<<blocks, 256>>>(x, ei);
    }
    stage_mma_kernel<<<152, STAGE_THREADS, SM_BYTES>>>(W1, b1, 1, 0);
    stage_mma_kernel<<<152, STAGE_THREADS, SM_BYTES>>>(W2, b2, 0, 1);
    bn_prep_kernel<<<1, 128>>>(gamma, beta);
    {
        int n4 = N_NODES * D / 4;
        bn_apply_kernel<<<(n4 + 255) / 256, 256>>>(out);
    }
}

// round 8
// speedup vs baseline: 1.2771x; 1.0573x over previous
#include <cuda_runtime.h>
#include <cuda_bf16.h>
#include <cstdint>
#include <math.h>

#define N_NODES 100000
#define D 128
#define E_EDGES 1600000
#define EPS 1e-5f
#define NT64 ((N_NODES + 63) / 64)   // 1563 tiles of 64 rows

// ---------------- scratch (device globals: no allocs allowed) ----------------
__device__ float  g_agg[(size_t)N_NODES * D];   // x + agg; then h2 (in-place)
__device__ double g_colsum[D];
__device__ double g_colsq [D];
__device__ float  g_scale[D];
__device__ float  g_shift[D];
__device__ int    g_idx_is64;

// ============================ helpers ========================================
__device__ __forceinline__ uint32_t smem_u32(const void* p) {
    uint32_t a;
    asm("{ .reg .u64 t; cvta.to.shared.u64 t, %1; cvt.u32.u64 %0, t; }"
        : "=r"(a) : "l"(p));
    return a;
}
// bf16 tile row=256B, j = 16B chunk: ldmatrix-phase-conflict-free swizzle
__device__ __forceinline__ int bswz(int r, int j) {
    return r * 256 + ((((j ^ r) & 7) | (j & 8)) << 4);
}
// f32 out tile swizzle (float index)
__device__ __forceinline__ int idxA(int row, int col) {
    return row * 128 + (((col >> 2) ^ (row & 31)) << 2) + (col & 3);
}
__device__ __forceinline__ void ldmx4(uint32_t r[4], uint32_t addr) {
    asm volatile("ldmatrix.sync.aligned.m8n8.x4.shared.b16 {%0,%1,%2,%3}, [%4];"
                 : "=r"(r[0]), "=r"(r[1]), "=r"(r[2]), "=r"(r[3]) : "r"(addr));
}
__device__ __forceinline__ void mma_bf16(float c[4], const uint32_t a[4],
                                         uint32_t b0, uint32_t b1) {
    asm volatile(
        "mma.sync.aligned.m16n8k16.row.col.f32.bf16.bf16.f32 "
        "{%0,%1,%2,%3}, {%4,%5,%6,%7}, {%8,%9}, {%0,%1,%2,%3};"
        : "+f"(c[0]), "+f"(c[1]), "+f"(c[2]), "+f"(c[3])
        : "r"(a[0]), "r"(a[1]), "r"(a[2]), "r"(a[3]), "r"(b0), "r"(b1));
}
__device__ __forceinline__ void cp_async16(uint32_t s, const void* g, int src_sz) {
    asm volatile("cp.async.cg.shared.global [%0], [%1], 16, %2;"
                 :: "r"(s), "l"(g), "r"(src_sz) : "memory");
}
__device__ __forceinline__ void cp_commit() {
    asm volatile("cp.async.commit_group;" ::: "memory");
}
__device__ __forceinline__ void cp_wait0() {
    asm volatile("cp.async.wait_group 0;" ::: "memory");
}
__device__ __forceinline__ uint32_t pack_hi(float a, float b) {
    __nv_bfloat16 h0 = __float2bfloat16(a), h1 = __float2bfloat16(b);
    return (uint32_t)__bfloat16_as_ushort(h0)
         | ((uint32_t)__bfloat16_as_ushort(h1) << 16);
}
__device__ __forceinline__ uint32_t pack_lo(float a, float b) {
    __nv_bfloat16 h0 = __float2bfloat16(a), h1 = __float2bfloat16(b);
    __nv_bfloat16 l0 = __float2bfloat16(a - __bfloat162float(h0));
    __nv_bfloat16 l1 = __float2bfloat16(b - __bfloat162float(h1));
    return (uint32_t)__bfloat16_as_ushort(l0)
         | ((uint32_t)__bfloat16_as_ushort(l1) << 16);
}

// ---------------- kernel 1: agg = x, zero BN accums, detect idx dtype -------
__global__ void init_kernel(const float* __restrict__ x,
                            const int* __restrict__ ei32) {
    size_t i = (size_t)blockIdx.x * blockDim.x + threadIdx.x;
    size_t n4 = (size_t)N_NODES * D / 4;
    if (i < n4)
        reinterpret_cast<float4*>(g_agg)[i] = reinterpret_cast<const float4*>(x)[i];
    if (blockIdx.x == 0 && threadIdx.x < D) {
        g_colsum[threadIdx.x] = 0.0;
        g_colsq [threadIdx.x] = 0.0;
    }
    if (blockIdx.x == 0 && threadIdx.x == 0) {
        int is64 = 1;
        #pragma unroll 1
        for (int k = 0; k < 128; k++)
            if (ei32[2 * k + 1] != 0) { is64 = 0; break; }
        g_idx_is64 = is64;
    }
}

// ---------------- kernel 2: scatter-add, one warp per edge ------------------
__device__ __forceinline__ void red_add_v4(float* addr, float4 v) {
    asm volatile("red.global.add.v4.f32 [%0], {%1,%2,%3,%4};"
                 :: "l"(addr), "f"(v.x), "f"(v.y), "f"(v.z), "f"(v.w) : "memory");
}
__global__ void scatter_kernel(const float* __restrict__ x,
                               const void* __restrict__ ei_raw) {
    int w    = (blockIdx.x * blockDim.x + threadIdx.x) >> 5;
    int lane = threadIdx.x & 31;
    if (w >= E_EDGES) return;
    int r, c;
    if (g_idx_is64) {
        const long long* ei = (const long long*)ei_raw;
        r = (int)__ldg(ei + w);
        c = (int)__ldg(ei + E_EDGES + w);
    } else {
        const int* ei = (const int*)ei_raw;
        r = __ldg(ei + w);
        c = __ldg(ei + E_EDGES + w);
    }
    float4 v = *reinterpret_cast<const float4*>(x + (size_t)c * D + lane * 4);
    red_add_v4(g_agg + (size_t)r * D + lane * 4, v);
}

// ---------------- fused MLP kernel: both GEMMs in one pass ------------------
// io <- (relu(io@W1+b1))@W2+b2, 64-row tiles, mid stays in smem.
#define MLP_THREADS 512
#define SO_W1H  0
#define SO_W1L  32768
#define SO_W2H  65536
#define SO_W2L  98304
#define SO_A    131072     // Ahi 16384 | Alo 16384 ; OUT f32 aliases all 32768
#define SO_MID  163840     // MIDhi 16384 | MIDlo 16384
#define SO_STG  196608     // raw f32 tile 64x128 = 32768
#define SO_B1   229376
#define SO_B2   229888
#define SO_CS   230400
#define SO_CQ   230912
#define SM_BYTES 231424

__global__ __launch_bounds__(MLP_THREADS, 1)
void fused_mlp_kernel(const float* __restrict__ W1, const float* __restrict__ b1,
                      const float* __restrict__ W2, const float* __restrict__ b2) {
    extern __shared__ char smc[];
    float* OUT = (float*)(smc + SO_A);
    float* STG = (float*)(smc + SO_STG);
    float* B1S = (float*)(smc + SO_B1);
    float* B2S = (float*)(smc + SO_B2);
    float* CS  = (float*)(smc + SO_CS);
    float* CQ  = (float*)(smc + SO_CQ);
    const uint32_t sb = smem_u32(smc);

    const int tid    = threadIdx.x;
    const int lane   = tid & 31;
    const int warp   = tid >> 5;       // 0..15
    const int warp_m = warp & 3;       // 4 row-blocks of 16
    const int warp_n = warp >> 2;      // 4 col-blocks of 32
    const int gid    = lane >> 2;
    const int tig    = lane & 3;

    float* io = g_agg;

    // ---- load both weight sets once: W[k][n] -> [n][k] bf16 hi/lo swizzled --
    for (int i4 = tid; i4 < 4096; i4 += MLP_THREADS) {
        int k  = i4 >> 5;
        int c4 = i4 & 31;
        float4 v1 = ((const float4*)W1)[i4];
        float4 v2 = ((const float4*)W2)[i4];
        #pragma unroll
        for (int e = 0; e < 4; e++) {
            float a = (e == 0) ? v1.x : (e == 1) ? v1.y : (e == 2) ? v1.z : v1.w;
            float b = (e == 0) ? v2.x : (e == 1) ? v2.y : (e == 2) ? v2.z : v2.w;
            int n = c4 * 4 + e;
            int off = bswz(n, k >> 3) + (k & 7) * 2;
            __nv_bfloat16 ah = __float2bfloat16(a);
            __nv_bfloat16 bh = __float2bfloat16(b);
            *(__nv_bfloat16*)(smc + SO_W1H + off) = ah;
            *(__nv_bfloat16*)(smc + SO_W1L + off) = __float2bfloat16(a - __bfloat162float(ah));
            *(__nv_bfloat16*)(smc + SO_W2H + off) = bh;
            *(__nv_bfloat16*)(smc + SO_W2L + off) = __float2bfloat16(b - __bfloat162float(bh));
        }
    }
    if (tid < 128) {
        B1S[tid] = b1[tid];
        B2S[tid] = b2[tid];
        CS[tid]  = 0.f;
        CQ[tid]  = 0.f;
    }

    // ---- prologue: prefetch first tile ---------------------------------------
    {
        int t0 = blockIdx.x;
        if (t0 < NT64) {
            int base = t0 << 6;
            #pragma unroll
            for (int q = 0; q < 4; q++) {
                int ch  = q * MLP_THREADS + tid;    // 2048 16B chunks
                int row = ch >> 5, c4 = ch & 31;
                int sz  = (base + row < N_NODES) ? 16 : 0;
                cp_async16(sb + SO_STG + ch * 16,
                           (const float4*)io + (size_t)(base + row) * 32 + c4, sz);
            }
        }
        cp_commit();
    }

    // fragment constants
    const int rA0 = warp_m * 16 + (lane & 15);
    const int jAh = lane >> 4;
    const int rB0 = warp_n * 32 + (lane & 7) + ((lane >> 4) << 3);
    const int jBh = (lane >> 3) & 1;

    for (int t = blockIdx.x; t < NT64; t += gridDim.x) {
        const int base  = t << 6;
        const int valid = min(64, N_NODES - base);

        cp_wait0();
        __syncthreads();   // STG ready; OUT (aliases A) fully stored prev iter

        // ---- 1) split STG -> Ahi/Alo bf16 ------------------------------------
        #pragma unroll
        for (int q = 0; q < 2; q++) {
            int f   = q * MLP_THREADS + tid;       // 1024 chunks of 8 floats
            int row = f >> 4, j = f & 15;
            const float4* src = (const float4*)(STG + row * 128 + j * 8);
            float4 v0 = src[0], v1 = src[1];
            uint32_t ph[4] = {pack_hi(v0.x, v0.y), pack_hi(v0.z, v0.w),
                              pack_hi(v1.x, v1.y), pack_hi(v1.z, v1.w)};
            uint32_t pl[4] = {pack_lo(v0.x, v0.y), pack_lo(v0.z, v0.w),
                              pack_lo(v1.x, v1.y), pack_lo(v1.z, v1.w)};
            int off = bswz(row, j);
            *(uint4*)(smc + SO_A + off)         = make_uint4(ph[0], ph[1], ph[2], ph[3]);
            *(uint4*)(smc + SO_A + 16384 + off) = make_uint4(pl[0], pl[1], pl[2], pl[3]);
        }
        __syncthreads();   // split done; STG free

        // ---- 1b) prefetch NEXT tile (overlaps both GEMMs) --------------------
        {
            int tn = t + gridDim.x;
            if (tn < NT64) {
                int nb = tn << 6;
                #pragma unroll
                for (int q = 0; q < 4; q++) {
                    int ch  = q * MLP_THREADS + tid;
                    int row = ch >> 5, c4 = ch & 31;
                    int sz  = (nb + row < N_NODES) ? 16 : 0;
                    cp_async16(sb + SO_STG + ch * 16,
                               (const float4*)io + (size_t)(nb + row) * 32 + c4, sz);
                }
            }
            cp_commit();
        }

        float c[4][4];

        // ================= GEMM 1: mid = relu(A @ W1 + b1) ====================
        #pragma unroll
        for (int j = 0; j < 4; j++)
            #pragma unroll
            for (int e = 0; e < 4; e++) c[j][e] = 0.f;

        #pragma unroll 2
        for (int s = 0; s < 8; s++) {
            int jA = (s << 1) | jAh;
            uint32_t offA = (uint32_t)(rA0 * 256 + ((((jA ^ rA0) & 7) | (jA & 8)) << 4));
            int jB = (s << 1) | jBh;
            uint32_t offB = (uint32_t)(rB0 * 256 + ((((jB ^ rB0) & 7) | (jB & 8)) << 4));

            uint32_t ah[4], al[4], bh[2][4], bl[2][4];
            ldmx4(ah, sb + SO_A + offA);
            ldmx4(al, sb + SO_A + 16384 + offA);
            ldmx4(bh[0], sb + SO_W1H + offB);
            ldmx4(bh[1], sb + SO_W1H + offB + 4096);
            ldmx4(bl[0], sb + SO_W1L + offB);
            ldmx4(bl[1], sb + SO_W1L + offB + 4096);

            #pragma unroll
            for (int j = 0; j < 4; j++) {
                int p = j >> 1, q2 = (j & 1) << 1;
                mma_bf16(c[j], ah, bh[p][q2], bh[p][q2 + 1]);
                mma_bf16(c[j], ah, bl[p][q2], bl[p][q2 + 1]);
                mma_bf16(c[j], al, bh[p][q2], bh[p][q2 + 1]);
            }
        }

        // ---- epilogue 1: bias+relu, split bf16 hi/lo -> MID ------------------
        {
            int r0 = warp_m * 16 + gid;
            #pragma unroll
            for (int j = 0; j < 4; j++) {
                int cc = warp_n * 32 + j * 8 + 2 * tig;
                float v0 = fmaxf(c[j][0] + B1S[cc],     0.f);
                float v1 = fmaxf(c[j][1] + B1S[cc + 1], 0.f);
                float v2 = fmaxf(c[j][2] + B1S[cc],     0.f);
                float v3 = fmaxf(c[j][3] + B1S[cc + 1], 0.f);
                int o0 = bswz(r0,     cc >> 3) + 4 * tig;
                int o1 = bswz(r0 + 8, cc >> 3) + 4 * tig;
                *(uint32_t*)(smc + SO_MID + o0)         = pack_hi(v0, v1);
                *(uint32_t*)(smc + SO_MID + 16384 + o0) = pack_lo(v0, v1);
                *(uint32_t*)(smc + SO_MID + o1)         = pack_hi(v2, v3);
                *(uint32_t*)(smc + SO_MID + 16384 + o1) = pack_lo(v2, v3);
            }
        }
        __syncthreads();   // MID visible to all warps

        // ================= GEMM 2: h2 = mid @ W2 + b2 =========================
        #pragma unroll
        for (int j = 0; j < 4; j++)
            #pragma unroll
            for (int e = 0; e < 4; e++) c[j][e] = 0.f;

        #pragma unroll 2
        for (int s = 0; s < 8; s++) {
            int jA = (s << 1) | jAh;
            uint32_t offA = (uint32_t)(rA0 * 256 + ((((jA ^ rA0) & 7) | (jA & 8)) << 4));
            int jB = (s << 1) | jBh;
            uint32_t offB = (uint32_t)(rB0 * 256 + ((((jB ^ rB0) & 7) | (jB & 8)) << 4));

            uint32_t ah[4], al[4], bh[2][4], bl[2][4];
            ldmx4(ah, sb + SO_MID + offA);
            ldmx4(al, sb + SO_MID + 16384 + offA);
            ldmx4(bh[0], sb + SO_W2H + offB);
            ldmx4(bh[1], sb + SO_W2H + offB + 4096);
            ldmx4(bl[0], sb + SO_W2L + offB);
            ldmx4(bl[1], sb + SO_W2L + offB + 4096);

            #pragma unroll
            for (int j = 0; j < 4; j++) {
                int p = j >> 1, q2 = (j & 1) << 1;
                mma_bf16(c[j], ah, bh[p][q2], bh[p][q2 + 1]);
                mma_bf16(c[j], ah, bl[p][q2], bl[p][q2 + 1]);
                mma_bf16(c[j], al, bh[p][q2], bh[p][q2 + 1]);
            }
        }

        // ---- epilogue 2: bias -> OUT f32 (aliases A region, reads done) ------
        {
            int r0 = warp_m * 16 + gid;
            #pragma unroll
            for (int j = 0; j < 4; j++) {
                int cc = warp_n * 32 + j * 8 + 2 * tig;
                float v0 = c[j][0] + B2S[cc];
                float v1 = c[j][1] + B2S[cc + 1];
                float v2 = c[j][2] + B2S[cc];
                float v3 = c[j][3] + B2S[cc + 1];
                *(float2*)&OUT[idxA(r0,     cc)] = make_float2(v0, v1);
                *(float2*)&OUT[idxA(r0 + 8, cc)] = make_float2(v2, v3);
            }
        }
        __syncthreads();   // OUT complete

        // ---- store tile + fused BN column sums --------------------------------
        {
            int col  = tid >> 2;
            int quar = tid & 3;
            int rbeg = quar * 16;
            int rend = min(rbeg + 16, valid);
            float s = 0.f, q = 0.f;
            for (int r = rbeg; r < rend; r++) {
                float v = OUT[idxA(r, col)];
                s += v; q += v * v;
            }
            atomicAdd(&CS[col], s);
            atomicAdd(&CQ[col], q);
        }
        #pragma unroll
        for (int q = 0; q < 4; q++) {
            int f   = q * MLP_THREADS + tid;      // 2048 float4
            int row = f >> 5, c4 = f & 31;
            if (row < valid) {
                int off = row * 128 + ((c4 ^ (row & 31)) << 2);
                float4 v = *(const float4*)(OUT + off);
                ((float4*)io)[(size_t)(base + row) * 32 + c4] = v;
            }
        }
        // top-of-loop sync orders OUT/A reuse
    }

    __syncthreads();
    if (tid < 128) {
        atomicAdd(&g_colsum[tid], (double)CS[tid]);
        atomicAdd(&g_colsq [tid], (double)CQ[tid]);
    }
}

// ---------------- BN coefficients -------------------------------------------
__global__ void bn_prep_kernel(const float* __restrict__ gamma,
                               const float* __restrict__ beta) {
    int j = threadIdx.x;
    if (j < D) {
        double mean = g_colsum[j] / (double)N_NODES;
        double var  = g_colsq[j] / (double)N_NODES - mean * mean;
        float inv   = rsqrtf((float)var + EPS);
        float sc    = gamma[j] * inv;
        g_scale[j]  = sc;
        g_shift[j]  = beta[j] - (float)mean * sc;
    }
}

// ---------------- apply BN ----------------------------------------------------
__global__ void bn_apply_kernel(float* __restrict__ out) {
    __shared__ float sc[D], sh[D];
    if (threadIdx.x < D) {
        sc[threadIdx.x] = g_scale[threadIdx.x];
        sh[threadIdx.x] = g_shift[threadIdx.x];
    }
    __syncthreads();
    size_t i  = (size_t)blockIdx.x * blockDim.x + threadIdx.x;
    size_t n4 = (size_t)N_NODES * D / 4;
    if (i < n4) {
        int c = (int)((i & 31) << 2);
        float4 h = reinterpret_cast<const float4*>(g_agg)[i];
        float4 o;
        o.x = h.x * sc[c + 0] + sh[c + 0];
        o.y = h.y * sc[c + 1] + sh[c + 1];
        o.z = h.z * sc[c + 2] + sh[c + 2];
        o.w = h.w * sc[c + 3] + sh[c + 3];
        reinterpret_cast<float4*>(out)[i] = o;
    }
}

// ---------------- launcher ----------------------------------------------------
extern "C" void kernel_launch(void* const* d_in, const int* in_sizes, int n_in,
                              void* d_out, int out_size) {
    const float* x     = (const float*)d_in[0];
    const void*  ei    = d_in[1];
    const float* W1    = (const float*)d_in[2];
    const float* b1    = (const float*)d_in[3];
    const float* W2    = (const float*)d_in[4];
    const float* b2    = (const float*)d_in[5];
    const float* gamma = (const float*)d_in[6];
    const float* beta  = (const float*)d_in[7];
    float* out = (float*)d_out;

    cudaFuncSetAttribute(fused_mlp_kernel,
                         cudaFuncAttributeMaxDynamicSharedMemorySize, SM_BYTES);

    {
        int n4 = N_NODES * D / 4;
        init_kernel<<<(n4 + 255) / 256, 256>>>(x, (const int*)ei);
    }
    {
        int blocks = (E_EDGES + 7) / 8;   // 8 warps (256 threads) per block
        scatter_kernel<<<blocks, 256>>>(x, ei);
    }
    fused_mlp_kernel<<<152, MLP_THREADS, SM_BYTES>>>(W1, b1, W2, b2);
    bn_prep_kernel<<<1, 128>>>(gamma, beta);
    {
        int n4 = N_NODES * D / 4;
        bn_apply_kernel<<<(n4 + 255) / 256, 256>>>(out);
    }
}